// round 2
// baseline (speedup 1.0000x reference)
#include <cuda_runtime.h>
#include <cstdint>

typedef unsigned long long u64;

#define Bsz    256
#define Ssz    512
#define Tsz    20
#define Esz    25
#define Hsz    128
#define SKIPsz 64
#define Gsz    512            // 4*H
#define NROWS  (Bsz*Ssz)      // 131072 ; row r = t*256 + b (t-major)

// ---------------- scratch (static device globals; no allocation) ----------
__device__ float g_xpool[(size_t)NROWS * Esz];        // [t*256+b][25]
__device__ float g_mask [(size_t)NROWS];              // [t*256+b]
__device__ float g_P    [(size_t)2 * NROWS * Gsz];    // [dir][t*256+b][512]
__device__ float g_out  [(size_t)NROWS * 256];        // [b*512+t][256] (f|b)
__device__ float g_hf   [(size_t)Bsz * Hsz];          // final fwd h
__device__ float g_qwq  [(size_t)Bsz * Hsz];          // h_fwd@Wq + bq
__device__ float g_energy[(size_t)NROWS];             // [b*512+t]

// ---------------- f32x2 helpers -------------------------------------------
__device__ __forceinline__ u64 pk(float a, float b) {
    u64 r;
    asm("mov.b64 %0, {%1, %2};" : "=l"(r) : "r"(__float_as_uint(a)), "r"(__float_as_uint(b)));
    return r;
}
__device__ __forceinline__ void upk(u64 v, float& a, float& b) {
    unsigned lo, hi;
    asm("mov.b64 {%0, %1}, %2;" : "=r"(lo), "=r"(hi) : "l"(v));
    a = __uint_as_float(lo); b = __uint_as_float(hi);
}
__device__ __forceinline__ void fma2(u64& d, u64 a, u64 b) {
    asm("fma.rn.f32x2 %0, %1, %2, %0;" : "+l"(d) : "l"(a), "l"(b));
}

// ---------------- math helpers --------------------------------------------
__device__ __forceinline__ float sigf(float x) {
    return __fdividef(1.f, 1.f + __expf(-x));
}
__device__ __forceinline__ float tanhpr(float x) {
    return __fdividef(2.f, 1.f + __expf(-2.f * x)) - 1.f;
}

// ================= K1: embedding mean-pool + step mask =====================
__global__ void k_embed(const int* __restrict__ tags, const float* __restrict__ emb) {
    int g    = blockIdx.x * 8 + (threadIdx.x >> 5);
    int lane = threadIdx.x & 31;
    if (g >= NROWS) return;
    int b = g >> 9, s = g & 511;
    const int* tg = tags + (size_t)g * Tsz;
    float acc = 0.f; int cnt = 0; int first = 0;
    #pragma unroll
    for (int i = 0; i < Tsz; i++) {
        int tv = __ldg(tg + i);
        if (i == 0) first = tv;
        if (tv != 0) {
            cnt++;
            if (lane < Esz) acc += __ldg(emb + (size_t)tv * Esz + lane);
        }
    }
    int r = s * Bsz + b;
    if (lane < Esz) g_xpool[(size_t)r * Esz + lane] = acc / (cnt ? (float)cnt : 1.f);
    if (lane == 0)  g_mask[r] = (first != 0) ? 1.f : 0.f;
}

// ================= K2: prologue GEMM  P = x@K + skip@Sk + bias =============
// inner dim padded 89 -> 96 (48 f32x2 pairs). Thread j owns gate column j.
__global__ __launch_bounds__(512, 1)
void k_prologue(const float* __restrict__ skips,
                const float* __restrict__ Kf, const float* __restrict__ Skf, const float* __restrict__ bf,
                const float* __restrict__ Kb, const float* __restrict__ Skb, const float* __restrict__ bb) {
    __shared__ __align__(16) u64 xs2[8][48];
    int j = threadIdx.x, d = blockIdx.y;
    const float* Kw = d ? Kb : Kf;
    const float* Sw = d ? Skb : Skf;
    const float* bw = d ? bb : bf;

    u64 wr[48];
    #pragma unroll
    for (int p = 0; p < 48; p++) {
        float a = 0.f, b2 = 0.f;
        int k0 = 2 * p, k1 = 2 * p + 1;
        if (k0 < Esz)      a  = __ldg(Kw + k0 * Gsz + j);
        else if (k0 < 89)  a  = __ldg(Sw + (k0 - Esz) * Gsz + j);
        if (k1 < Esz)      b2 = __ldg(Kw + k1 * Gsz + j);
        else if (k1 < 89)  b2 = __ldg(Sw + (k1 - Esz) * Gsz + j);
        wr[p] = pk(a, b2);
    }
    float bias = __ldg(bw + j);
    float* Pd = g_P + (size_t)d * NROWS * Gsz;

    int r0 = blockIdx.x * 1792;
    for (int rt = 0; rt < 1792; rt += 8) {
        int rb = r0 + rt;
        if (rb >= NROWS) break;
        __syncthreads();
        if (j < 384) {
            int rr = j / 48, p = j % 48;
            int r = rb + rr;
            float a = 0.f, b2 = 0.f;
            if (r < NROWS) {
                int bb2 = r & 255, tt = r >> 8;
                int k0 = 2 * p, k1 = 2 * p + 1;
                if (k0 < Esz)     a  = g_xpool[(size_t)r * Esz + k0];
                else if (k0 < 89) a  = __ldg(skips + ((size_t)(bb2 << 9) + tt) * SKIPsz + (k0 - Esz));
                if (k1 < Esz)     b2 = g_xpool[(size_t)r * Esz + k1];
                else if (k1 < 89) b2 = __ldg(skips + ((size_t)(bb2 << 9) + tt) * SKIPsz + (k1 - Esz));
            }
            xs2[rr][p] = pk(a, b2);
        }
        __syncthreads();
        #pragma unroll 1
        for (int rr = 0; rr < 8; rr++) {
            int r = rb + rr;
            if (r >= NROWS) break;
            u64 z0 = pk(bias, 0.f), z1 = pk(0.f, 0.f);
            #pragma unroll
            for (int q = 0; q < 24; q++) {
                ulonglong2 xv = *(const ulonglong2*)&xs2[rr][2 * q];
                fma2(z0, xv.x, wr[2 * q]);
                fma2(z1, xv.y, wr[2 * q + 1]);
            }
            float l0, h0, l1, h1; upk(z0, l0, h0); upk(z1, l1, h1);
            Pd[(size_t)r * Gsz + j] = (l0 + h0) + (l1 + h1);
        }
    }
}

// ================= K3: LSTM recurrence ======================================
// grid (128, 2): block = (2 batches, dir). 512 threads; thread j owns col j.
// R rows 0..79 in 40 packed regs; rows 80..127 packed in smem.
#define LSTM_SMEM (98304 + 1024 + 4096)
__global__ __launch_bounds__(512, 1)
void k_lstm(const float* __restrict__ Rf, const float* __restrict__ Rb) {
    extern __shared__ __align__(16) char smraw[];
    ulonglong2* R4  = (ulonglong2*)smraw;                    // [w*512 + j], w=0..11 (rows 80+4w..83+4w)
    u64*        h2s = (u64*)(smraw + 98304);                 // [p*2 + nb], p=0..63 pairs
    float*      z_sm = (float*)(smraw + 98304 + 1024);       // [nb*512 + col]

    int j = threadIdx.x, d = blockIdx.y, bg = blockIdx.x;
    const float* R = d ? Rb : Rf;

    u64 Rp[40];
    #pragma unroll
    for (int p = 0; p < 40; p++)
        Rp[p] = pk(__ldg(R + (2 * p) * Gsz + j), __ldg(R + (2 * p + 1) * Gsz + j));
    #pragma unroll 1
    for (int w = 0; w < 12; w++) {
        int r0 = 80 + 4 * w;
        ulonglong2 v;
        v.x = pk(__ldg(R + (r0 + 0) * Gsz + j), __ldg(R + (r0 + 1) * Gsz + j));
        v.y = pk(__ldg(R + (r0 + 2) * Gsz + j), __ldg(R + (r0 + 3) * Gsz + j));
        R4[w * 512 + j] = v;
    }
    if (j < 128) h2s[j] = 0ULL;

    float c = 0.f, hp = 0.f;
    const float* Pd = g_P + (size_t)d * NROWS * Gsz;
    int t = d ? (Ssz - 1) : 0;
    int dt = d ? -1 : 1;
    float pv0 = Pd[((size_t)(t * Bsz + 2 * bg + 0)) * Gsz + j];
    float pv1 = Pd[((size_t)(t * Bsz + 2 * bg + 1)) * Gsz + j];
    __syncthreads();

    #pragma unroll 1
    for (int i = 0; i < Ssz; i++) {
        u64 z0 = pk(pv0, 0.f), z1 = pk(pv1, 0.f);
        #pragma unroll
        for (int p = 0; p < 40; p++) {
            ulonglong2 hv = *(const ulonglong2*)&h2s[p * 2];
            fma2(z0, hv.x, Rp[p]);
            fma2(z1, hv.y, Rp[p]);
        }
        #pragma unroll
        for (int w = 0; w < 12; w++) {
            ulonglong2 rv = R4[w * 512 + j];
            int p = 40 + 2 * w;
            ulonglong2 ha = *(const ulonglong2*)&h2s[p * 2];
            ulonglong2 hb = *(const ulonglong2*)&h2s[p * 2 + 2];
            fma2(z0, ha.x, rv.x); fma2(z1, ha.y, rv.x);
            fma2(z0, hb.x, rv.y); fma2(z1, hb.y, rv.y);
        }
        { float lo, hi; upk(z0, lo, hi); z_sm[j]       = lo + hi;
          upk(z1, lo, hi);               z_sm[512 + j] = lo + hi; }

        float pn0 = 0.f, pn1 = 0.f;
        int tn = t + dt;
        if (i < Ssz - 1) {
            pn0 = Pd[((size_t)(tn * Bsz + 2 * bg + 0)) * Gsz + j];
            pn1 = Pd[((size_t)(tn * Bsz + 2 * bg + 1)) * Gsz + j];
        }
        __syncthreads();
        if (j < 256) {
            int nb = j >> 7, jj = j & 127;
            int b  = 2 * bg + nb;
            float m = g_mask[t * Bsz + b];
            const float* zz = z_sm + nb * 512;
            float zi = zz[jj], zf = zz[jj + 128], zg = zz[jj + 256], zo = zz[jj + 384];
            float cn = sigf(zf) * c + sigf(zi) * tanhpr(zg);
            float hn = sigf(zo) * tanhpr(cn);
            bool mm = (m != 0.f);
            float h2v = mm ? hn : hp;
            c  = mm ? cn : c;
            hp = h2v;
            g_out[(((size_t)b << 9) + t) * 256 + (d << 7) + jj] = h2v;
            if (d == 0 && i == Ssz - 1) g_hf[b * Hsz + jj] = h2v;
            float hnb = __shfl_down_sync(0xffffffffu, h2v, 1);
            if ((jj & 1) == 0) h2s[(jj >> 1) * 2 + nb] = pk(h2v, hnb);
        }
        __syncthreads();
        pv0 = pn0; pv1 = pn1; t = tn;
    }
}

// ================= K4: queries = h_fwd @ Wq + bq ============================
__global__ void k_qw(const float* __restrict__ Wq, const float* __restrict__ bq) {
    __shared__ float hf[Hsz];
    int b = blockIdx.x, i = threadIdx.x;
    hf[i] = g_hf[b * Hsz + i];
    __syncthreads();
    float acc = __ldg(bq + i);
    #pragma unroll 8
    for (int k = 0; k < Hsz; k++) acc = fmaf(hf[k], __ldg(Wq + k * Hsz + i), acc);
    g_qwq[b * Hsz + i] = acc;
}

// ================= K5: keys GEMM + tanh + energy ============================
// grid 1024 (4 blocks per batch b, 128 rows each). Wk resident in smem.
#define KEYS_SMEM (131072 + 4096 + 512 + 512 + 2048 + 64)
__global__ __launch_bounds__(256, 1)
void k_keys(const float* __restrict__ Wk, const float* __restrict__ bk,
            const float* __restrict__ We, const float* __restrict__ be) {
    extern __shared__ __align__(16) char ksraw[];
    u64*   Wk2  = (u64*)ksraw;                         // [p*128 + i], p=0..127 pairs over k
    u64*   row2 = (u64*)(ksraw + 131072);              // [ro*128 + p], 4 rows
    float* qb   = (float*)(ksraw + 131072 + 4096);     // 128
    float* bks  = qb + 128;                            // 128
    float* z2s  = bks + 128;                           // [ro*128 + jc]
    float* part = z2s + 512;                           // [ro*4 + warp]

    int tid = threadIdx.x;
    int jc = tid & 127, half = tid >> 7;
    int blk = blockIdx.x;
    int b = blk >> 2;
    int r0 = blk * 128;

    for (int e = tid; e < 128 * 128; e += 256) {
        int p = e >> 7, i = e & 127;
        Wk2[e] = pk(__ldg(Wk + (2 * p) * Hsz + i), __ldg(Wk + (2 * p + 1) * Hsz + i));
    }
    if (tid < 128) { qb[tid] = g_qwq[b * Hsz + tid]; bks[tid] = __ldg(bk + tid); }
    float Wej = (tid < 128) ? __ldg(We + tid) : 0.f;
    float bev = __ldg(be);
    __syncthreads();

    #pragma unroll 1
    for (int rr = 0; rr < 128; rr += 4) {
        // stage 4 rows of out (256 floats each) as pairs
        for (int e = tid; e < 512; e += 256) {
            int ro = e >> 7, p = e & 127;
            const float2 v = *(const float2*)(g_out + (size_t)(r0 + rr + ro) * 256 + 2 * p);
            row2[e] = pk(v.x, v.y);
        }
        __syncthreads();

        u64 a0 = pk(0.f, 0.f), a1 = a0, a2 = a0, a3 = a0;
        int pbase = half << 6;
        #pragma unroll
        for (int q = 0; q < 32; q++) {
            int p = pbase + 2 * q;
            u64 w0 = Wk2[(size_t)p * 128 + jc];
            u64 w1 = Wk2[(size_t)(p + 1) * 128 + jc];
            ulonglong2 r_0 = *(const ulonglong2*)&row2[0 * 128 + p];
            ulonglong2 r_1 = *(const ulonglong2*)&row2[1 * 128 + p];
            ulonglong2 r_2 = *(const ulonglong2*)&row2[2 * 128 + p];
            ulonglong2 r_3 = *(const ulonglong2*)&row2[3 * 128 + p];
            fma2(a0, r_0.x, w0); fma2(a0, r_0.y, w1);
            fma2(a1, r_1.x, w0); fma2(a1, r_1.y, w1);
            fma2(a2, r_2.x, w0); fma2(a2, r_2.y, w1);
            fma2(a3, r_3.x, w0); fma2(a3, r_3.y, w1);
        }
        float acc[4];
        { float lo, hi;
          upk(a0, lo, hi); acc[0] = lo + hi;
          upk(a1, lo, hi); acc[1] = lo + hi;
          upk(a2, lo, hi); acc[2] = lo + hi;
          upk(a3, lo, hi); acc[3] = lo + hi; }
        if (half) {
            #pragma unroll
            for (int ro = 0; ro < 4; ro++) z2s[ro * 128 + jc] = acc[ro];
        }
        __syncthreads();
        if (tid < 128) {
            #pragma unroll
            for (int ro = 0; ro < 4; ro++) {
                float z = acc[ro] + z2s[ro * 128 + jc] + bks[jc] + qb[jc];
                float v = Wej * tanhpr(z);
                #pragma unroll
                for (int o = 16; o > 0; o >>= 1) v += __shfl_down_sync(0xffffffffu, v, o);
                if ((tid & 31) == 0) part[ro * 4 + (tid >> 5)] = v;
            }
        }
        __syncthreads();
        if (tid < 4) {
            float e = part[tid * 4 + 0] + part[tid * 4 + 1] + part[tid * 4 + 2] + part[tid * 4 + 3] + bev;
            int r2 = r0 + rr + tid;
            int tt = r2 & 511;
            float m = g_mask[tt * Bsz + b];
            g_energy[r2] = e - (1.f - m) * 1e9f;
        }
        __syncthreads();
    }
}

// ================= K6: softmax over t + context =============================
__global__ __launch_bounds__(256, 1)
void k_softctx(float* __restrict__ out) {
    __shared__ float wsm[512];
    __shared__ float red[256];
    int b = blockIdx.x, tid = threadIdx.x;
    float e0 = g_energy[(size_t)b * 512 + tid];
    float e1 = g_energy[(size_t)b * 512 + 256 + tid];
    red[tid] = fmaxf(e0, e1);
    __syncthreads();
    #pragma unroll
    for (int o = 128; o > 0; o >>= 1) {
        if (tid < o) red[tid] = fmaxf(red[tid], red[tid + o]);
        __syncthreads();
    }
    float mx = red[0];
    __syncthreads();
    float x0 = __expf(e0 - mx), x1 = __expf(e1 - mx);
    wsm[tid] = x0; wsm[256 + tid] = x1;
    red[tid] = x0 + x1;
    __syncthreads();
    #pragma unroll
    for (int o = 128; o > 0; o >>= 1) {
        if (tid < o) red[tid] += red[tid + o];
        __syncthreads();
    }
    float inv = __fdividef(1.f, red[0]);

    const float* ob = g_out + (size_t)b * 512 * 256;
    float acc = 0.f;
    #pragma unroll 4
    for (int t = 0; t < 512; t++)
        acc = fmaf(wsm[t], __ldg(ob + (size_t)t * 256 + tid), acc);
    out[(size_t)b * 256 + tid] = acc * inv;
}

// ================= launch ===================================================
extern "C" void kernel_launch(void* const* d_in, const int* in_sizes, int n_in,
                              void* d_out, int out_size) {
    const int*   tags  = (const int*)  d_in[0];
    const float* skips = (const float*)d_in[1];
    const float* emb   = (const float*)d_in[2];
    const float* Kf    = (const float*)d_in[3];
    const float* Rf    = (const float*)d_in[4];
    const float* Skf   = (const float*)d_in[5];
    const float* bf    = (const float*)d_in[6];
    const float* Kb    = (const float*)d_in[7];
    const float* Rb    = (const float*)d_in[8];
    const float* Skb   = (const float*)d_in[9];
    const float* bb    = (const float*)d_in[10];
    const float* Wk    = (const float*)d_in[11];
    const float* bk    = (const float*)d_in[12];
    const float* Wq    = (const float*)d_in[13];
    const float* bq    = (const float*)d_in[14];
    const float* We    = (const float*)d_in[15];
    const float* be    = (const float*)d_in[16];
    float* out = (float*)d_out;

    cudaFuncSetAttribute(k_lstm, cudaFuncAttributeMaxDynamicSharedMemorySize, LSTM_SMEM);
    cudaFuncSetAttribute(k_keys, cudaFuncAttributeMaxDynamicSharedMemorySize, KEYS_SMEM);

    k_embed<<<NROWS / 8, 256>>>(tags, emb);
    k_prologue<<<dim3(74, 2), 512>>>(skips, Kf, Skf, bf, Kb, Skb, bb);
    k_lstm<<<dim3(128, 2), 512, LSTM_SMEM>>>(Rf, Rb);
    k_qw<<<Bsz, Hsz>>>(Wq, bq);
    k_keys<<<1024, 256, KEYS_SMEM>>>(Wk, bk, We, be);
    k_softctx<<<Bsz, 256>>>(out);
}

// round 3
// speedup vs baseline: 1.2369x; 1.2369x over previous
#include <cuda_runtime.h>
#include <cstdint>

typedef unsigned long long u64;

#define Bsz    256
#define Ssz    512
#define Tsz    20
#define Esz    25
#define Hsz    128
#define SKIPsz 64
#define Gsz    512            // 4*H
#define NROWS  (Bsz*Ssz)      // 131072 ; row r = t*256 + b (t-major)

// ---------------- scratch (static device globals; no allocation) ----------
__device__ float g_xpool[(size_t)NROWS * Esz];        // [t*256+b][25]
__device__ float g_mask [(size_t)NROWS];              // [t*256+b]
__device__ float g_P    [(size_t)2 * NROWS * Gsz];    // [dir][t*256+b][512]
__device__ float g_out  [(size_t)NROWS * 256];        // [b*512+t][256] (f|b)
__device__ float g_hf   [(size_t)Bsz * Hsz];          // final fwd h
__device__ float g_qwq  [(size_t)Bsz * Hsz];          // h_fwd@Wq + bq
__device__ float g_energy[(size_t)NROWS];             // [b*512+t]

// ---------------- f32x2 helpers -------------------------------------------
__device__ __forceinline__ u64 pk(float a, float b) {
    u64 r;
    asm("mov.b64 %0, {%1, %2};" : "=l"(r) : "r"(__float_as_uint(a)), "r"(__float_as_uint(b)));
    return r;
}
__device__ __forceinline__ void upk(u64 v, float& a, float& b) {
    unsigned lo, hi;
    asm("mov.b64 {%0, %1}, %2;" : "=r"(lo), "=r"(hi) : "l"(v));
    a = __uint_as_float(lo); b = __uint_as_float(hi);
}
__device__ __forceinline__ void fma2(u64& d, u64 a, u64 b) {
    asm("fma.rn.f32x2 %0, %1, %2, %0;" : "+l"(d) : "l"(a), "l"(b));
}

// ---------------- math helpers --------------------------------------------
__device__ __forceinline__ float sigf(float x) {
    return __fdividef(1.f, 1.f + __expf(-x));
}
__device__ __forceinline__ float tanhpr(float x) {
    return __fdividef(2.f, 1.f + __expf(-2.f * x)) - 1.f;
}

// ================= K1: embedding mean-pool + step mask =====================
__global__ void k_embed(const int* __restrict__ tags, const float* __restrict__ emb) {
    int g    = blockIdx.x * 8 + (threadIdx.x >> 5);
    int lane = threadIdx.x & 31;
    if (g >= NROWS) return;
    int b = g >> 9, s = g & 511;
    const int* tg = tags + (size_t)g * Tsz;
    float acc = 0.f; int cnt = 0; int first = 0;
    #pragma unroll
    for (int i = 0; i < Tsz; i++) {
        int tv = __ldg(tg + i);
        if (i == 0) first = tv;
        if (tv != 0) {
            cnt++;
            if (lane < Esz) acc += __ldg(emb + (size_t)tv * Esz + lane);
        }
    }
    int r = s * Bsz + b;
    if (lane < Esz) g_xpool[(size_t)r * Esz + lane] = acc / (cnt ? (float)cnt : 1.f);
    if (lane == 0)  g_mask[r] = (first != 0) ? 1.f : 0.f;
}

// ================= K2: prologue GEMM  P = x@K + skip@Sk + bias =============
__global__ __launch_bounds__(512, 1)
void k_prologue(const float* __restrict__ skips,
                const float* __restrict__ Kf, const float* __restrict__ Skf, const float* __restrict__ bf,
                const float* __restrict__ Kb, const float* __restrict__ Skb, const float* __restrict__ bb) {
    __shared__ __align__(16) u64 xs2[8][48];
    int j = threadIdx.x, d = blockIdx.y;
    const float* Kw = d ? Kb : Kf;
    const float* Sw = d ? Skb : Skf;
    const float* bw = d ? bb : bf;

    u64 wr[48];
    #pragma unroll
    for (int p = 0; p < 48; p++) {
        float a = 0.f, b2 = 0.f;
        int k0 = 2 * p, k1 = 2 * p + 1;
        if (k0 < Esz)      a  = __ldg(Kw + k0 * Gsz + j);
        else if (k0 < 89)  a  = __ldg(Sw + (k0 - Esz) * Gsz + j);
        if (k1 < Esz)      b2 = __ldg(Kw + k1 * Gsz + j);
        else if (k1 < 89)  b2 = __ldg(Sw + (k1 - Esz) * Gsz + j);
        wr[p] = pk(a, b2);
    }
    float bias = __ldg(bw + j);
    float* Pd = g_P + (size_t)d * NROWS * Gsz;

    int r0 = blockIdx.x * 1792;
    for (int rt = 0; rt < 1792; rt += 8) {
        int rb = r0 + rt;
        if (rb >= NROWS) break;
        __syncthreads();
        if (j < 384) {
            int rr = j / 48, p = j % 48;
            int r = rb + rr;
            float a = 0.f, b2 = 0.f;
            if (r < NROWS) {
                int bb2 = r & 255, tt = r >> 8;
                int k0 = 2 * p, k1 = 2 * p + 1;
                if (k0 < Esz)     a  = g_xpool[(size_t)r * Esz + k0];
                else if (k0 < 89) a  = __ldg(skips + ((size_t)(bb2 << 9) + tt) * SKIPsz + (k0 - Esz));
                if (k1 < Esz)     b2 = g_xpool[(size_t)r * Esz + k1];
                else if (k1 < 89) b2 = __ldg(skips + ((size_t)(bb2 << 9) + tt) * SKIPsz + (k1 - Esz));
            }
            xs2[rr][p] = pk(a, b2);
        }
        __syncthreads();
        #pragma unroll 1
        for (int rr = 0; rr < 8; rr++) {
            int r = rb + rr;
            if (r >= NROWS) break;
            u64 z0 = pk(bias, 0.f), z1 = pk(0.f, 0.f);
            #pragma unroll
            for (int q = 0; q < 24; q++) {
                ulonglong2 xv = *(const ulonglong2*)&xs2[rr][2 * q];
                fma2(z0, xv.x, wr[2 * q]);
                fma2(z1, xv.y, wr[2 * q + 1]);
            }
            float l0, h0, l1, h1; upk(z0, l0, h0); upk(z1, l1, h1);
            Pd[(size_t)r * Gsz + j] = (l0 + h0) + (l1 + h1);
        }
    }
}

// ================= K3: LSTM recurrence ======================================
// grid (64, 2): block = (4 batches, dir), 1 full wave on 148 SMs.
// 512 threads; thread j owns gate column j for all 4 batches.
// R rows 0..79 in 40 packed regs; rows 80..127 packed in smem.
#define LSTM_SMEM (98304 + 2048 + 8192 + 8192)
__global__ __launch_bounds__(512, 1)
void k_lstm(const float* __restrict__ Rf, const float* __restrict__ Rb) {
    extern __shared__ __align__(16) char smraw[];
    ulonglong2* R4  = (ulonglong2*)smraw;                    // [w*512 + j], w=0..11 -> rows 80+4w..83+4w
    u64*        h2s = (u64*)(smraw + 98304);                 // [p*4 + nb], p=0..63 pairs, nb=0..3
    float*      z_sm = (float*)(smraw + 98304 + 2048);       // [nb*512 + col]
    float*      msk  = (float*)(smraw + 98304 + 2048 + 8192);// [t*4 + nb]

    int j = threadIdx.x, d = blockIdx.y, bg = blockIdx.x;
    const float* R = d ? Rb : Rf;

    u64 Rp[40];
    #pragma unroll
    for (int p = 0; p < 40; p++)
        Rp[p] = pk(__ldg(R + (2 * p) * Gsz + j), __ldg(R + (2 * p + 1) * Gsz + j));
    #pragma unroll 1
    for (int w = 0; w < 12; w++) {
        int r0 = 80 + 4 * w;
        ulonglong2 v;
        v.x = pk(__ldg(R + (r0 + 0) * Gsz + j), __ldg(R + (r0 + 1) * Gsz + j));
        v.y = pk(__ldg(R + (r0 + 2) * Gsz + j), __ldg(R + (r0 + 3) * Gsz + j));
        R4[w * 512 + j] = v;
    }
    if (j < 256) h2s[j] = 0ULL;
    // preload step masks for the 4 batches
    for (int e = j; e < 2048; e += 512)
        msk[e] = g_mask[(e >> 2) * Bsz + 4 * bg + (e & 3)];

    int nb = j >> 7, jj = j & 127;
    int b  = 4 * bg + nb;
    float c = 0.f, hp = 0.f;
    const float* Pd = g_P + (size_t)d * NROWS * Gsz;
    int t = d ? (Ssz - 1) : 0;
    int dt = d ? -1 : 1;
    float pv0 = Pd[((size_t)(t * Bsz + 4 * bg + 0)) * Gsz + j];
    float pv1 = Pd[((size_t)(t * Bsz + 4 * bg + 1)) * Gsz + j];
    float pv2 = Pd[((size_t)(t * Bsz + 4 * bg + 2)) * Gsz + j];
    float pv3 = Pd[((size_t)(t * Bsz + 4 * bg + 3)) * Gsz + j];
    __syncthreads();

    #pragma unroll 1
    for (int i = 0; i < Ssz; i++) {
        u64 z0 = pk(pv0, 0.f), z1 = pk(pv1, 0.f), z2 = pk(pv2, 0.f), z3 = pk(pv3, 0.f);
        #pragma unroll
        for (int p = 0; p < 40; p++) {
            ulonglong2 ha = *(const ulonglong2*)&h2s[p * 4];
            ulonglong2 hb = *(const ulonglong2*)&h2s[p * 4 + 2];
            fma2(z0, ha.x, Rp[p]); fma2(z1, ha.y, Rp[p]);
            fma2(z2, hb.x, Rp[p]); fma2(z3, hb.y, Rp[p]);
        }
        #pragma unroll
        for (int w = 0; w < 12; w++) {
            ulonglong2 rv = R4[w * 512 + j];
            int p = 40 + 2 * w;
            ulonglong2 ha = *(const ulonglong2*)&h2s[p * 4];
            ulonglong2 hb = *(const ulonglong2*)&h2s[p * 4 + 2];
            ulonglong2 hc = *(const ulonglong2*)&h2s[p * 4 + 4];
            ulonglong2 hd = *(const ulonglong2*)&h2s[p * 4 + 6];
            fma2(z0, ha.x, rv.x); fma2(z1, ha.y, rv.x);
            fma2(z2, hb.x, rv.x); fma2(z3, hb.y, rv.x);
            fma2(z0, hc.x, rv.y); fma2(z1, hc.y, rv.y);
            fma2(z2, hd.x, rv.y); fma2(z3, hd.y, rv.y);
        }
        { float lo, hi;
          upk(z0, lo, hi); z_sm[j]        = lo + hi;
          upk(z1, lo, hi); z_sm[512 + j]  = lo + hi;
          upk(z2, lo, hi); z_sm[1024 + j] = lo + hi;
          upk(z3, lo, hi); z_sm[1536 + j] = lo + hi; }

        float pn0 = 0.f, pn1 = 0.f, pn2 = 0.f, pn3 = 0.f;
        int tn = t + dt;
        if (i < Ssz - 1) {
            pn0 = Pd[((size_t)(tn * Bsz + 4 * bg + 0)) * Gsz + j];
            pn1 = Pd[((size_t)(tn * Bsz + 4 * bg + 1)) * Gsz + j];
            pn2 = Pd[((size_t)(tn * Bsz + 4 * bg + 2)) * Gsz + j];
            pn3 = Pd[((size_t)(tn * Bsz + 4 * bg + 3)) * Gsz + j];
        }
        __syncthreads();
        {
            float m = msk[t * 4 + nb];
            const float* zz = z_sm + nb * 512;
            float zi = zz[jj], zf = zz[jj + 128], zg = zz[jj + 256], zo = zz[jj + 384];
            float cn = sigf(zf) * c + sigf(zi) * tanhpr(zg);
            float hn = sigf(zo) * tanhpr(cn);
            bool mm = (m != 0.f);
            float h2v = mm ? hn : hp;
            c  = mm ? cn : c;
            hp = h2v;
            g_out[(((size_t)b << 9) + t) * 256 + (d << 7) + jj] = h2v;
            if (d == 0 && i == Ssz - 1) g_hf[b * Hsz + jj] = h2v;
            float hnb = __shfl_down_sync(0xffffffffu, h2v, 1);
            if ((jj & 1) == 0) h2s[(jj >> 1) * 4 + nb] = pk(h2v, hnb);
        }
        __syncthreads();
        pv0 = pn0; pv1 = pn1; pv2 = pn2; pv3 = pn3; t = tn;
    }
}

// ================= K4: queries = h_fwd @ Wq + bq ============================
__global__ void k_qw(const float* __restrict__ Wq, const float* __restrict__ bq) {
    __shared__ float hf[Hsz];
    int b = blockIdx.x, i = threadIdx.x;
    hf[i] = g_hf[b * Hsz + i];
    __syncthreads();
    float acc = __ldg(bq + i);
    #pragma unroll 8
    for (int k = 0; k < Hsz; k++) acc = fmaf(hf[k], __ldg(Wq + k * Hsz + i), acc);
    g_qwq[b * Hsz + i] = acc;
}

// ================= K5: keys GEMM + tanh + energy ============================
// grid 1024 (4 blocks per batch b, 128 rows each). 512 threads:
// thread = (k-quarter qtr 0..3, col jc 0..127); Wk quarter in 32 packed regs.
__global__ __launch_bounds__(512, 1)
void k_keys(const float* __restrict__ Wk, const float* __restrict__ bk,
            const float* __restrict__ We, const float* __restrict__ be) {
    __shared__ __align__(16) u64 row2[4][128];      // 4 staged rows as k-pairs
    __shared__ float qb[128], bks[128];
    __shared__ float partial[3][4][128];
    __shared__ float part2[4][4];

    int tid = threadIdx.x;
    int jc = tid & 127, qtr = tid >> 7;
    int blk = blockIdx.x;
    int b = blk >> 2;
    int r0 = blk * 128;

    u64 wq[32];
    #pragma unroll
    for (int i = 0; i < 32; i++) {
        int k0 = qtr * 64 + 2 * i;
        wq[i] = pk(__ldg(Wk + (size_t)k0 * Hsz + jc), __ldg(Wk + (size_t)(k0 + 1) * Hsz + jc));
    }
    if (tid < 128) { qb[tid] = g_qwq[b * Hsz + tid]; bks[tid] = __ldg(bk + tid); }
    float Wej = __ldg(We + jc);
    float bev = __ldg(be);
    __syncthreads();

    #pragma unroll 1
    for (int rr = 0; rr < 128; rr += 4) {
        // stage 4 rows (each 256 floats = 128 pairs); 512 threads, 1 entry each
        {
            int ro = tid >> 7, p = tid & 127;
            const float2 v = *(const float2*)(g_out + (size_t)(r0 + rr + ro) * 256 + 2 * p);
            row2[ro][p] = pk(v.x, v.y);
        }
        __syncthreads();

        u64 a0 = pk(0.f, 0.f), a1 = a0, a2 = a0, a3 = a0;
        #pragma unroll
        for (int it = 0; it < 16; it++) {
            int p = qtr * 32 + 2 * it;
            u64 w0 = wq[2 * it], w1 = wq[2 * it + 1];
            ulonglong2 r_0 = *(const ulonglong2*)&row2[0][p];
            ulonglong2 r_1 = *(const ulonglong2*)&row2[1][p];
            ulonglong2 r_2 = *(const ulonglong2*)&row2[2][p];
            ulonglong2 r_3 = *(const ulonglong2*)&row2[3][p];
            fma2(a0, r_0.x, w0); fma2(a0, r_0.y, w1);
            fma2(a1, r_1.x, w0); fma2(a1, r_1.y, w1);
            fma2(a2, r_2.x, w0); fma2(a2, r_2.y, w1);
            fma2(a3, r_3.x, w0); fma2(a3, r_3.y, w1);
        }
        float acc[4];
        { float lo, hi;
          upk(a0, lo, hi); acc[0] = lo + hi;
          upk(a1, lo, hi); acc[1] = lo + hi;
          upk(a2, lo, hi); acc[2] = lo + hi;
          upk(a3, lo, hi); acc[3] = lo + hi; }
        if (qtr > 0) {
            #pragma unroll
            for (int ro = 0; ro < 4; ro++) partial[qtr - 1][ro][jc] = acc[ro];
        }
        __syncthreads();
        if (qtr == 0) {
            #pragma unroll
            for (int ro = 0; ro < 4; ro++) {
                float z = acc[ro] + partial[0][ro][jc] + partial[1][ro][jc] + partial[2][ro][jc]
                        + bks[jc] + qb[jc];
                float v = Wej * tanhpr(z);
                #pragma unroll
                for (int o = 16; o > 0; o >>= 1) v += __shfl_down_sync(0xffffffffu, v, o);
                if ((jc & 31) == 0) part2[ro][jc >> 5] = v;
            }
        }
        __syncthreads();
        if (tid < 4) {
            float e = part2[tid][0] + part2[tid][1] + part2[tid][2] + part2[tid][3] + bev;
            int r2 = r0 + rr + tid;
            int tt = r2 & 511;
            float m = g_mask[tt * Bsz + b];
            g_energy[r2] = e - (1.f - m) * 1e9f;
        }
        __syncthreads();
    }
}

// ================= K6: softmax over t + context =============================
__global__ __launch_bounds__(256, 1)
void k_softctx(float* __restrict__ out) {
    __shared__ float wsm[512];
    __shared__ float red[256];
    int b = blockIdx.x, tid = threadIdx.x;
    float e0 = g_energy[(size_t)b * 512 + tid];
    float e1 = g_energy[(size_t)b * 512 + 256 + tid];
    red[tid] = fmaxf(e0, e1);
    __syncthreads();
    #pragma unroll
    for (int o = 128; o > 0; o >>= 1) {
        if (tid < o) red[tid] = fmaxf(red[tid], red[tid + o]);
        __syncthreads();
    }
    float mx = red[0];
    __syncthreads();
    float x0 = __expf(e0 - mx), x1 = __expf(e1 - mx);
    wsm[tid] = x0; wsm[256 + tid] = x1;
    red[tid] = x0 + x1;
    __syncthreads();
    #pragma unroll
    for (int o = 128; o > 0; o >>= 1) {
        if (tid < o) red[tid] += red[tid + o];
        __syncthreads();
    }
    float inv = __fdividef(1.f, red[0]);

    const float* ob = g_out + (size_t)b * 512 * 256;
    float acc = 0.f;
    #pragma unroll 4
    for (int t = 0; t < 512; t++)
        acc = fmaf(wsm[t], __ldg(ob + (size_t)t * 256 + tid), acc);
    out[(size_t)b * 256 + tid] = acc * inv;
}

// ================= launch ===================================================
extern "C" void kernel_launch(void* const* d_in, const int* in_sizes, int n_in,
                              void* d_out, int out_size) {
    const int*   tags  = (const int*)  d_in[0];
    const float* skips = (const float*)d_in[1];
    const float* emb   = (const float*)d_in[2];
    const float* Kf    = (const float*)d_in[3];
    const float* Rf    = (const float*)d_in[4];
    const float* Skf   = (const float*)d_in[5];
    const float* bf    = (const float*)d_in[6];
    const float* Kb    = (const float*)d_in[7];
    const float* Rb    = (const float*)d_in[8];
    const float* Skb   = (const float*)d_in[9];
    const float* bb    = (const float*)d_in[10];
    const float* Wk    = (const float*)d_in[11];
    const float* bk    = (const float*)d_in[12];
    const float* Wq    = (const float*)d_in[13];
    const float* bq    = (const float*)d_in[14];
    const float* We    = (const float*)d_in[15];
    const float* be    = (const float*)d_in[16];
    float* out = (float*)d_out;

    cudaFuncSetAttribute(k_lstm, cudaFuncAttributeMaxDynamicSharedMemorySize, LSTM_SMEM);

    k_embed<<<NROWS / 8, 256>>>(tags, emb);
    k_prologue<<<dim3(74, 2), 512>>>(skips, Kf, Skf, bf, Kb, Skb, bb);
    k_lstm<<<dim3(64, 2), 512, LSTM_SMEM>>>(Rf, Rb);
    k_qw<<<Bsz, Hsz>>>(Wq, bq);
    k_keys<<<1024, 512>>>(Wk, bk, We, be);
    k_softctx<<<Bsz, 256>>>(out);
}